// round 2
// baseline (speedup 1.0000x reference)
#include <cuda_runtime.h>
#include <cstdint>

#define B_ 64
#define T_ 1024
#define I_ 256
#define H_ 512

// ---------------- static device scratch (no dynamic allocation) ----------------
// Projections stored transposed: [t][j][b]  -> index (t*H_ + j)*B_ + b
__device__ float g_xz[(size_t)T_ * H_ * B_];
__device__ float g_xr[(size_t)T_ * H_ * B_];
__device__ float g_xh[(size_t)T_ * H_ * B_];
// Hidden state double buffer + r*h exchange buffer, layout [j][b]
__device__ float g_h[2][H_ * B_];
__device__ float g_rh[H_ * B_];
// Grid barrier state
__device__ unsigned g_bar_count;
__device__ unsigned g_bar_gen;

// ---------------- grid-wide barrier (sense via increasing generation) ----------
__device__ __forceinline__ void grid_sync_(unsigned nblocks) {
    __threadfence();          // make this thread's global writes visible
    __syncthreads();          // all threads of block arrived + fenced
    if (threadIdx.x == 0) {
        volatile unsigned* genp = &g_bar_gen;
        unsigned gen = *genp;
        if (atomicAdd(&g_bar_count, 1u) == nblocks - 1u) {
            atomicExch(&g_bar_count, 0u);
            __threadfence();
            atomicExch(&g_bar_gen, gen + 1u);
        } else {
            while (*genp == gen) { __nanosleep(64); }
        }
    }
    __syncthreads();
    __threadfence();
}

// =================================================================================
// Init: zero h0
// =================================================================================
__global__ void gru_init_kernel() {
    int idx = blockIdx.x * blockDim.x + threadIdx.x;
    if (idx < H_ * B_) {
        g_h[0][idx] = 0.f;
        g_h[1][idx] = 0.f;
    }
}

// =================================================================================
// Projection GEMM:  out_g[t][n][b] = xs[b][t][:] . Wg[0:I][n] + bias_g[n]
// m = b*T + t runs 0..65535.  128x128 tile, BK=8, 256 threads, 8x8 microtile.
// =================================================================================
__global__ __launch_bounds__(256) void gru_proj_kernel(
    const float* __restrict__ xs,
    const float* __restrict__ Wz, const float* __restrict__ Wr, const float* __restrict__ Wh,
    const float* __restrict__ bz, const float* __restrict__ br, const float* __restrict__ bh)
{
    __shared__ float As[8 * 132];
    __shared__ float Bs[8 * 132];

    const int g = blockIdx.z;
    const float* W    = (g == 0) ? Wz : (g == 1) ? Wr : Wh;
    const float* bias = (g == 0) ? bz : (g == 1) ? br : bh;
    float*       out  = (g == 0) ? g_xz : (g == 1) ? g_xr : g_xh;

    const int m0 = blockIdx.x * 128;
    const int n0 = blockIdx.y * 128;
    const int tid = (int)threadIdx.x;

    const int tx = tid & 15;      // n microtile
    const int ty = tid >> 4;      // m microtile

    const int arow = tid >> 1, aseg = tid & 1;           // A loader
    const int brow = tid >> 5, bcol4 = (tid & 31) * 4;   // B loader

    float acc[8][8];
#pragma unroll
    for (int i = 0; i < 8; ++i)
#pragma unroll
        for (int j = 0; j < 8; ++j) acc[i][j] = 0.f;

    for (int k0 = 0; k0 < I_; k0 += 8) {
        float4 av = *(const float4*)&xs[(size_t)(m0 + arow) * I_ + k0 + aseg * 4];
        float4 bv = *(const float4*)&W[(size_t)(k0 + brow) * H_ + n0 + bcol4];
        __syncthreads();   // previous tile fully consumed
        As[(aseg * 4 + 0) * 132 + arow] = av.x;
        As[(aseg * 4 + 1) * 132 + arow] = av.y;
        As[(aseg * 4 + 2) * 132 + arow] = av.z;
        As[(aseg * 4 + 3) * 132 + arow] = av.w;
        *(float4*)&Bs[brow * 132 + bcol4] = bv;
        __syncthreads();
#pragma unroll
        for (int kk = 0; kk < 8; ++kk) {
            float a[8], b[8];
            float4 a0 = *(const float4*)&As[kk * 132 + ty * 8];
            float4 a1 = *(const float4*)&As[kk * 132 + ty * 8 + 4];
            float4 b0 = *(const float4*)&Bs[kk * 132 + tx * 8];
            float4 b1 = *(const float4*)&Bs[kk * 132 + tx * 8 + 4];
            a[0]=a0.x; a[1]=a0.y; a[2]=a0.z; a[3]=a0.w;
            a[4]=a1.x; a[5]=a1.y; a[6]=a1.z; a[7]=a1.w;
            b[0]=b0.x; b[1]=b0.y; b[2]=b0.z; b[3]=b0.w;
            b[4]=b1.x; b[5]=b1.y; b[6]=b1.z; b[7]=b1.w;
#pragma unroll
            for (int i = 0; i < 8; ++i)
#pragma unroll
                for (int j = 0; j < 8; ++j) acc[i][j] += a[i] * b[j];
        }
    }

#pragma unroll
    for (int j = 0; j < 8; ++j) {
        const int n = n0 + tx * 8 + j;
        const float bia = bias[n];
#pragma unroll
        for (int i = 0; i < 8; ++i) {
            const int m = m0 + ty * 8 + i;
            const int t = m & (T_ - 1);
            const int b = m >> 10;
            out[(size_t)(t * H_ + n) * B_ + b] = acc[i][j] + bia;
        }
    }
}

// =================================================================================
// Persistent recurrence kernel: 128 CTAs x 256 threads, 1 CTA/SM.
// CTA c owns columns [c*4, c*4+4) for all three gates.
// =================================================================================
#define NCTA 128
#define HS_STRIDE 65           // h_s[k*65 + b], bank = (k+b)&31
#define WS_STRIDE 13           // w_s[k*13 + g], bank = (13k+g)&31 (13 coprime 32)
#define SMEM_FLOATS (H_ * HS_STRIDE + H_ * WS_STRIDE + 256 + 256)
#define SMEM_BYTES  (SMEM_FLOATS * 4)

__device__ __forceinline__ float sigmoidf_(float x) {
    return 1.0f / (1.0f + expf(-x));
}

__global__ __launch_bounds__(256, 1) void gru_rec_kernel(
    const float* __restrict__ Wz, const float* __restrict__ Wr, const float* __restrict__ Wh,
    float* __restrict__ out)
{
    extern __shared__ float smem[];
    float* h_s  = smem;                         // H_ * 65
    float* w_s  = h_s + H_ * HS_STRIDE;         // H_ * 13
    float* z_s  = w_s + H_ * WS_STRIDE;         // 64*4
    float* hk_s = z_s + 256;                    // 64*4

    const int tid  = (int)threadIdx.x;
    const int w    = tid >> 5;
    const int lane = tid & 31;
    const int col0 = (int)blockIdx.x * 4;

    // ---- one-time: stage this CTA's 12 weight columns into smem ----
    for (int i = tid; i < H_ * 12; i += 256) {
        const int k = i / 12, g = i % 12;
        const float* W = (g < 4) ? Wz : (g < 8) ? Wr : Wh;
        w_s[k * WS_STRIDE + g] = W[(size_t)(I_ + k) * H_ + col0 + (g & 3)];
    }
    // g_h[0] is zeroed by init kernel (prior launch => visible)

    const int bbase = w * 8;
    const int bl = lane >> 2;            // batch-local 0..7
    const int jj = lane & 3;             // col-local 0..3
    const int b_ep = bbase + bl;         // epilogue batch
    const int jg_ep = col0 + jj;         // epilogue global col

#pragma unroll 1
    for (int t = 0; t < T_; ++t) {
        // ================= stage h (layout [k][b]) =================
        {
            const float4* src = (const float4*)g_h[t & 1];
            __syncthreads();   // also covers w_s staging on first iter
            for (int i = tid; i < H_ * (B_ / 4); i += 256) {
                const int k = i >> 4, b4 = (i & 15) << 2;
                float4 v = __ldcg(&src[i]);
                float* d = &h_s[k * HS_STRIDE + b4];
                d[0] = v.x; d[1] = v.y; d[2] = v.z; d[3] = v.w;
            }
            __syncthreads();
        }

        // ================= phase A: z, r dots (8 outputs x 8 batches / warp) ====
        float acc[64];
#pragma unroll
        for (int i = 0; i < 64; ++i) acc[i] = 0.f;
#pragma unroll 4
        for (int it = 0; it < 16; ++it) {
            const int k = lane + (it << 5);
            float wv[8], hv[8];
#pragma unroll
            for (int c = 0; c < 8; ++c) wv[c] = w_s[k * WS_STRIDE + c];
#pragma unroll
            for (int b = 0; b < 8; ++b) hv[b] = h_s[k * HS_STRIDE + bbase + b];
#pragma unroll
            for (int c = 0; c < 8; ++c)
#pragma unroll
                for (int b = 0; b < 8; ++b) acc[c * 8 + b] += wv[c] * hv[b];
        }
#pragma unroll
        for (int off = 16; off; off >>= 1)
#pragma unroll
            for (int i = 0; i < 64; ++i)
                acc[i] += __shfl_xor_sync(0xffffffffu, acc[i], off);

        // epilogue: each lane handles one (b, j)
        {
            const float hz = acc[jj * 8 + bl];
            const float hr = acc[(4 + jj) * 8 + bl];
            const size_t xi = (size_t)(t * H_ + jg_ep) * B_ + b_ep;
            const float z = sigmoidf_(__ldcg(&g_xz[xi]) + hz);
            const float r = sigmoidf_(__ldcg(&g_xr[xi]) + hr);
            const float hold = h_s[jg_ep * HS_STRIDE + b_ep];
            z_s[b_ep * 4 + jj]  = z;
            hk_s[b_ep * 4 + jj] = hold;
            __stcg(&g_rh[jg_ep * B_ + b_ep], r * hold);
        }
        grid_sync_(NCTA);

        // ================= stage rh into h_s =================
        {
            const float4* src = (const float4*)g_rh;
            for (int i = tid; i < H_ * (B_ / 4); i += 256) {
                const int k = i >> 4, b4 = (i & 15) << 2;
                float4 v = __ldcg(&src[i]);
                float* d = &h_s[k * HS_STRIDE + b4];
                d[0] = v.x; d[1] = v.y; d[2] = v.z; d[3] = v.w;
            }
            __syncthreads();
        }

        // ================= phase B: candidate dots (4 outputs x 8 batches / warp)
        float accB[32];
#pragma unroll
        for (int i = 0; i < 32; ++i) accB[i] = 0.f;
#pragma unroll 4
        for (int it = 0; it < 16; ++it) {
            const int k = lane + (it << 5);
            float wv[4], hv[8];
#pragma unroll
            for (int c = 0; c < 4; ++c) wv[c] = w_s[k * WS_STRIDE + 8 + c];
#pragma unroll
            for (int b = 0; b < 8; ++b) hv[b] = h_s[k * HS_STRIDE + bbase + b];
#pragma unroll
            for (int c = 0; c < 4; ++c)
#pragma unroll
                for (int b = 0; b < 8; ++b) accB[c * 8 + b] += wv[c] * hv[b];
        }
#pragma unroll
        for (int off = 16; off; off >>= 1)
#pragma unroll
            for (int i = 0; i < 32; ++i)
                accB[i] += __shfl_xor_sync(0xffffffffu, accB[i], off);

        // combine + write h_next, hs output
        {
            const float cand = accB[jj * 8 + bl];
            const size_t xi = (size_t)(t * H_ + jg_ep) * B_ + b_ep;
            const float xhv = __ldcg(&g_xh[xi]);
            const float z    = z_s[b_ep * 4 + jj];
            const float hold = hk_s[b_ep * 4 + jj];
            const float ht = tanhf(xhv + cand);
            const float hn = (1.0f - z) * hold + z * ht;
            __stcg(&out[(size_t)b_ep * T_ * H_ + (size_t)t * H_ + jg_ep], hn);
            __stcg(&g_h[(t + 1) & 1][jg_ep * B_ + b_ep], hn);
            if (t == T_ - 1)
                __stcg(&out[(size_t)B_ * T_ * H_ + (size_t)b_ep * H_ + jg_ep], hn);
        }
        grid_sync_(NCTA);
    }
}

// =================================================================================
extern "C" void kernel_launch(void* const* d_in, const int* in_sizes, int n_in,
                              void* d_out, int out_size) {
    const float* xs = (const float*)d_in[0];
    const float* Wz = (const float*)d_in[1];
    const float* bz = (const float*)d_in[2];
    const float* Wr = (const float*)d_in[3];
    const float* br = (const float*)d_in[4];
    const float* Wh = (const float*)d_in[5];
    const float* bh = (const float*)d_in[6];
    float* out = (float*)d_out;

    cudaFuncSetAttribute(gru_rec_kernel,
                         cudaFuncAttributeMaxDynamicSharedMemorySize, SMEM_BYTES);

    gru_init_kernel<<<(H_ * B_ + 511) / 512, 512>>>();

    dim3 pg(T_ * B_ / 128, H_ / 128, 3);
    gru_proj_kernel<<<pg, 256>>>(xs, Wz, Wr, Wh, bz, br, bh);

    gru_rec_kernel<<<NCTA, 256, SMEM_BYTES>>>(Wz, Wr, Wh, out);
}

// round 3
// speedup vs baseline: 1.8186x; 1.8186x over previous
#include <cuda_runtime.h>
#include <cstdint>

#define B_ 64
#define T_ 1024
#define I_ 256
#define H_ 512

// ---------------- static device scratch (no dynamic allocation) ----------------
// Projections stored transposed: [t][j][b]  -> index (t*H_ + j)*B_ + b
__device__ float g_xz[(size_t)T_ * H_ * B_];
__device__ float g_xr[(size_t)T_ * H_ * B_];
__device__ float g_xh[(size_t)T_ * H_ * B_];
// Hidden state double buffer + r*h exchange buffer, layout [b][j]
__device__ float g_h[2][B_ * H_];
__device__ float g_rh[B_ * H_];
// Grid barrier state
__device__ unsigned g_bar_count;
__device__ unsigned g_bar_gen;

// ---------------- grid-wide barrier (sense via increasing generation) ----------
__device__ __forceinline__ void grid_sync_(unsigned nblocks) {
    __threadfence();
    __syncthreads();
    if (threadIdx.x == 0) {
        volatile unsigned* genp = &g_bar_gen;
        unsigned gen = *genp;
        if (atomicAdd(&g_bar_count, 1u) == nblocks - 1u) {
            atomicExch(&g_bar_count, 0u);
            __threadfence();
            atomicExch(&g_bar_gen, gen + 1u);
        } else {
            while (*genp == gen) {}
        }
    }
    __syncthreads();
    __threadfence();
}

// =================================================================================
__global__ void gru_init_kernel() {
    int idx = blockIdx.x * blockDim.x + threadIdx.x;
    if (idx < H_ * B_) {
        g_h[0][idx] = 0.f;
        g_h[1][idx] = 0.f;
    }
}

// =================================================================================
// Projection GEMM:  out_g[t][n][b] = xs[b][t][:] . Wg[0:I][n] + bias_g[n]
// =================================================================================
__global__ __launch_bounds__(256) void gru_proj_kernel(
    const float* __restrict__ xs,
    const float* __restrict__ Wz, const float* __restrict__ Wr, const float* __restrict__ Wh,
    const float* __restrict__ bz, const float* __restrict__ br, const float* __restrict__ bh)
{
    __shared__ float As[8 * 132];
    __shared__ float Bs[8 * 132];

    const int g = blockIdx.z;
    const float* W    = (g == 0) ? Wz : (g == 1) ? Wr : Wh;
    const float* bias = (g == 0) ? bz : (g == 1) ? br : bh;
    float*       out  = (g == 0) ? g_xz : (g == 1) ? g_xr : g_xh;

    const int m0 = blockIdx.x * 128;
    const int n0 = blockIdx.y * 128;
    const int tid = (int)threadIdx.x;

    const int tx = tid & 15;
    const int ty = tid >> 4;

    const int arow = tid >> 1, aseg = tid & 1;
    const int brow = tid >> 5, bcol4 = (tid & 31) * 4;

    float acc[8][8];
#pragma unroll
    for (int i = 0; i < 8; ++i)
#pragma unroll
        for (int j = 0; j < 8; ++j) acc[i][j] = 0.f;

    for (int k0 = 0; k0 < I_; k0 += 8) {
        float4 av = *(const float4*)&xs[(size_t)(m0 + arow) * I_ + k0 + aseg * 4];
        float4 bv = *(const float4*)&W[(size_t)(k0 + brow) * H_ + n0 + bcol4];
        __syncthreads();
        As[(aseg * 4 + 0) * 132 + arow] = av.x;
        As[(aseg * 4 + 1) * 132 + arow] = av.y;
        As[(aseg * 4 + 2) * 132 + arow] = av.z;
        As[(aseg * 4 + 3) * 132 + arow] = av.w;
        *(float4*)&Bs[brow * 132 + bcol4] = bv;
        __syncthreads();
#pragma unroll
        for (int kk = 0; kk < 8; ++kk) {
            float a[8], b[8];
            float4 a0 = *(const float4*)&As[kk * 132 + ty * 8];
            float4 a1 = *(const float4*)&As[kk * 132 + ty * 8 + 4];
            float4 b0 = *(const float4*)&Bs[kk * 132 + tx * 8];
            float4 b1 = *(const float4*)&Bs[kk * 132 + tx * 8 + 4];
            a[0]=a0.x; a[1]=a0.y; a[2]=a0.z; a[3]=a0.w;
            a[4]=a1.x; a[5]=a1.y; a[6]=a1.z; a[7]=a1.w;
            b[0]=b0.x; b[1]=b0.y; b[2]=b0.z; b[3]=b0.w;
            b[4]=b1.x; b[5]=b1.y; b[6]=b1.z; b[7]=b1.w;
#pragma unroll
            for (int i = 0; i < 8; ++i)
#pragma unroll
                for (int j = 0; j < 8; ++j) acc[i][j] += a[i] * b[j];
        }
    }

#pragma unroll
    for (int j = 0; j < 8; ++j) {
        const int n = n0 + tx * 8 + j;
        const float bia = bias[n];
#pragma unroll
        for (int i = 0; i < 8; ++i) {
            const int m = m0 + ty * 8 + i;
            const int t = m & (T_ - 1);
            const int b = m >> 10;
            out[(size_t)(t * H_ + n) * B_ + b] = acc[i][j] + bia;
        }
    }
}

// =================================================================================
// Persistent recurrence kernel: 128 CTAs x 256 threads, 1 CTA/SM.
// CTA c owns columns [c*4, c*4+4) for all three gates.
// =================================================================================
#define NCTA 128
#define HS_S 520               // h_s[b*520 + k]; FMA loads bank = (8b + k)&31, conflict-free
#define WS_S 13                // w_s[k*13 + g]
#define SMEM_FLOATS (B_ * HS_S + H_ * WS_S + 256 + 256)
#define SMEM_BYTES  (SMEM_FLOATS * 4)

__device__ __forceinline__ float sigmoidf_(float x) {
    return 1.0f / (1.0f + expf(-x));
}

// exchange-and-specialize butterfly stage: live register count N halves;
// lanes with (lane & M) keep upper half indices, others lower.
#define RSTAGE(arr, N, M, lane)                                              \
    {                                                                        \
        const bool hi_ = ((lane) & (M)) != 0;                                \
        _Pragma("unroll")                                                    \
        for (int i_ = 0; i_ < (N); ++i_) {                                   \
            float send_ = hi_ ? arr[i_] : arr[i_ + (N)];                     \
            float recv_ = __shfl_xor_sync(0xffffffffu, send_, (M));          \
            arr[i_] = (hi_ ? arr[i_ + (N)] : arr[i_]) + recv_;               \
        }                                                                    \
    }

// Stage 32768 floats (8192 float4) from src into h_s[b*HS_S + k], src layout [b][k].
__device__ __forceinline__ void stage_h_(float* h_s, const float4* __restrict__ src, int tid) {
#pragma unroll 1
    for (int blk = 0; blk < 4; ++blk) {
        float4 v[8];
#pragma unroll
        for (int u = 0; u < 8; ++u)
            v[u] = __ldcg(src + tid + (blk * 8 + u) * 256);
#pragma unroll
        for (int u = 0; u < 8; ++u) {
            const int i = tid + (blk * 8 + u) * 256;
            const int b = i >> 7;                // 128 float4 per batch row
            const int k4 = (i & 127) << 2;
            *(float4*)&h_s[b * HS_S + k4] = v[u];
        }
    }
}

__global__ __launch_bounds__(256, 1) void gru_rec_kernel(
    const float* __restrict__ Wz, const float* __restrict__ Wr, const float* __restrict__ Wh,
    float* __restrict__ out)
{
    extern __shared__ float smem[];
    float* h_s  = smem;                       // B_ * 520
    float* w_s  = h_s + B_ * HS_S;            // H_ * 13
    float* z_s  = w_s + H_ * WS_S;            // 64*4
    float* hk_s = z_s + 256;                  // 64*4

    const int tid  = (int)threadIdx.x;
    const int w    = tid >> 5;
    const int lane = tid & 31;
    const int col0 = (int)blockIdx.x * 4;
    const int bbase = w * 8;

    // one-time: stage this CTA's 12 weight columns into smem
    for (int i = tid; i < H_ * 12; i += 256) {
        const int k = i / 12, g = i % 12;
        const float* W = (g < 4) ? Wz : (g < 8) ? Wr : Wh;
        w_s[k * WS_S + g] = W[(size_t)(I_ + k) * H_ + col0 + (g & 3)];
    }

    // per-lane epilogue mappings
    const int cA  = lane >> 2;               // 0..7: 0-3 -> z col, 4-7 -> r col
    const int jA  = cA & 3;
    const int b0A = bbase + 2 * (lane & 3);  // even batch pair
    const int bB  = bbase + (lane >> 2);     // phase-B: one (b, c) per lane
    const int cB  = lane & 3;

    const float* xpA_base = (cA < 4) ? g_xz : g_xr;

#pragma unroll 1
    for (int t = 0; t < T_; ++t) {
        // ---- stage h (layout [b][k]) ----
        __syncthreads();   // h_s free (covers w_s staging on iter 0)
        stage_h_(h_s, (const float4*)g_h[t & 1], tid);
        // prefetch phase-A gate operands (needed ~4K cycles from now)
        float2 xpA = __ldcg((const float2*)&xpA_base[((size_t)t * H_ + col0 + jA) * B_ + b0A]);
        __syncthreads();

        // ---- phase A: z,r dots; 8 gate-cols x 8 batches per warp, k-split 32 ----
        float acc[64];
#pragma unroll
        for (int i = 0; i < 64; ++i) acc[i] = 0.f;
#pragma unroll 4
        for (int it = 0; it < 16; ++it) {
            const int k = lane + (it << 5);
            float wv[8], hv[8];
#pragma unroll
            for (int c = 0; c < 8; ++c) wv[c] = w_s[k * WS_S + c];
#pragma unroll
            for (int b = 0; b < 8; ++b) hv[b] = h_s[(bbase + b) * HS_S + k];
#pragma unroll
            for (int c = 0; c < 8; ++c)
#pragma unroll
                for (int b = 0; b < 8; ++b) acc[c * 8 + b] += wv[c] * hv[b];
        }
        // reduce: lane l ends with acc idx {2l, 2l+1} = (c = l>>2, b = 2(l&3)+{0,1})
        RSTAGE(acc, 32, 16, lane)
        RSTAGE(acc, 16,  8, lane)
        RSTAGE(acc,  8,  4, lane)
        RSTAGE(acc,  4,  2, lane)
        RSTAGE(acc,  2,  1, lane)

        if (cA < 4) {   // z gate
            const float z0 = sigmoidf_(xpA.x + acc[0]);
            const float z1 = sigmoidf_(xpA.y + acc[1]);
            z_s[b0A * 4 + jA]       = z0;
            z_s[(b0A + 1) * 4 + jA] = z1;
        } else {        // r gate: compute r*h, publish
            const float r0 = sigmoidf_(xpA.x + acc[0]);
            const float r1 = sigmoidf_(xpA.y + acc[1]);
            const float h0 = h_s[b0A * HS_S + col0 + jA];
            const float h1 = h_s[(b0A + 1) * HS_S + col0 + jA];
            hk_s[b0A * 4 + jA]       = h0;
            hk_s[(b0A + 1) * 4 + jA] = h1;
            __stcg(&g_rh[(size_t)b0A * H_ + col0 + jA], r0 * h0);
            __stcg(&g_rh[(size_t)(b0A + 1) * H_ + col0 + jA], r1 * h1);
        }
        grid_sync_(NCTA);

        // ---- stage r*h ----
        stage_h_(h_s, (const float4*)g_rh, tid);
        float xpB = __ldcg(&g_xh[((size_t)t * H_ + col0 + cB) * B_ + bB]);
        __syncthreads();

        // ---- phase B: candidate dots; 4 cols x 8 batches per warp ----
        float accB[32];
#pragma unroll
        for (int i = 0; i < 32; ++i) accB[i] = 0.f;
#pragma unroll 4
        for (int it = 0; it < 16; ++it) {
            const int k = lane + (it << 5);
            float wv[4], hv[8];
#pragma unroll
            for (int c = 0; c < 4; ++c) wv[c] = w_s[k * WS_S + 8 + c];
#pragma unroll
            for (int b = 0; b < 8; ++b) hv[b] = h_s[(bbase + b) * HS_S + k];
#pragma unroll
            for (int b = 0; b < 8; ++b)
#pragma unroll
                for (int c = 0; c < 4; ++c) accB[b * 4 + c] += wv[c] * hv[b];
        }
        // reduce: lane l ends with accB idx l = (b = l>>2, c = l&3)
        RSTAGE(accB, 16, 16, lane)
        RSTAGE(accB,  8,  8, lane)
        RSTAGE(accB,  4,  4, lane)
        RSTAGE(accB,  2,  2, lane)
        RSTAGE(accB,  1,  1, lane)

        {
            const float z    = z_s[bB * 4 + cB];
            const float hold = hk_s[bB * 4 + cB];
            const float ht = tanhf(xpB + accB[0]);
            const float hn = fmaf(z, ht - hold, hold);
            out[(size_t)bB * T_ * H_ + (size_t)t * H_ + col0 + cB] = hn;
            __stcg(&g_h[(t + 1) & 1][(size_t)bB * H_ + col0 + cB], hn);
            if (t == T_ - 1)
                out[(size_t)B_ * T_ * H_ + (size_t)bB * H_ + col0 + cB] = hn;
        }
        grid_sync_(NCTA);
    }
}

// =================================================================================
extern "C" void kernel_launch(void* const* d_in, const int* in_sizes, int n_in,
                              void* d_out, int out_size) {
    const float* xs = (const float*)d_in[0];
    const float* Wz = (const float*)d_in[1];
    const float* bz = (const float*)d_in[2];
    const float* Wr = (const float*)d_in[3];
    const float* br = (const float*)d_in[4];
    const float* Wh = (const float*)d_in[5];
    const float* bh = (const float*)d_in[6];
    float* out = (float*)d_out;

    cudaFuncSetAttribute(gru_rec_kernel,
                         cudaFuncAttributeMaxDynamicSharedMemorySize, SMEM_BYTES);

    gru_init_kernel<<<(H_ * B_ + 511) / 512, 512>>>();

    dim3 pg(T_ * B_ / 128, H_ / 128, 3);
    gru_proj_kernel<<<pg, 256>>>(xs, Wz, Wr, Wh, bz, br, bh);

    gru_rec_kernel<<<NCTA, 256, SMEM_BYTES>>>(Wz, Wr, Wh, out);
}

// round 4
// speedup vs baseline: 2.2022x; 1.2109x over previous
#include <cuda_runtime.h>
#include <cstdint>

#define B_ 64
#define T_ 1024
#define I_ 256
#define H_ 512

// ---------------- static device scratch (no dynamic allocation) ----------------
// Projections stored transposed: [t][j][b]  -> index (t*H_ + j)*B_ + b
__device__ float g_xz[(size_t)T_ * H_ * B_];
__device__ float g_xr[(size_t)T_ * H_ * B_];
__device__ float g_xh[(size_t)T_ * H_ * B_];
// Hidden state double buffer + r*h exchange buffer, layout [b][j]
__device__ float g_h[2][B_ * H_];
__device__ float g_rh[B_ * H_];
// Grid barrier state
__device__ unsigned g_bar_count;
__device__ unsigned g_bar_gen;

// ---------------- grid-wide barrier (sense via increasing generation) ----------
__device__ __forceinline__ void grid_sync_(unsigned nblocks) {
    __threadfence();
    __syncthreads();
    if (threadIdx.x == 0) {
        volatile unsigned* genp = &g_bar_gen;
        unsigned gen = *genp;
        if (atomicAdd(&g_bar_count, 1u) == nblocks - 1u) {
            atomicExch(&g_bar_count, 0u);
            __threadfence();
            atomicExch(&g_bar_gen, gen + 1u);
        } else {
            while (*genp == gen) {}
        }
    }
    __syncthreads();
    __threadfence();
}

// =================================================================================
__global__ void gru_init_kernel() {
    int idx = blockIdx.x * blockDim.x + threadIdx.x;
    if (idx < H_ * B_) {
        g_h[0][idx] = 0.f;
        g_h[1][idx] = 0.f;
    }
}

// =================================================================================
// Projection GEMM:  out_g[t][n][b] = xs[b][t][:] . Wg[0:I][n] + bias_g[n]
// =================================================================================
__global__ __launch_bounds__(256) void gru_proj_kernel(
    const float* __restrict__ xs,
    const float* __restrict__ Wz, const float* __restrict__ Wr, const float* __restrict__ Wh,
    const float* __restrict__ bz, const float* __restrict__ br, const float* __restrict__ bh)
{
    __shared__ float As[8 * 132];
    __shared__ float Bs[8 * 132];

    const int g = blockIdx.z;
    const float* W    = (g == 0) ? Wz : (g == 1) ? Wr : Wh;
    const float* bias = (g == 0) ? bz : (g == 1) ? br : bh;
    float*       out  = (g == 0) ? g_xz : (g == 1) ? g_xr : g_xh;

    const int m0 = blockIdx.x * 128;
    const int n0 = blockIdx.y * 128;
    const int tid = (int)threadIdx.x;

    const int tx = tid & 15;
    const int ty = tid >> 4;

    const int arow = tid >> 1, aseg = tid & 1;
    const int brow = tid >> 5, bcol4 = (tid & 31) * 4;

    float acc[8][8];
#pragma unroll
    for (int i = 0; i < 8; ++i)
#pragma unroll
        for (int j = 0; j < 8; ++j) acc[i][j] = 0.f;

    for (int k0 = 0; k0 < I_; k0 += 8) {
        float4 av = *(const float4*)&xs[(size_t)(m0 + arow) * I_ + k0 + aseg * 4];
        float4 bv = *(const float4*)&W[(size_t)(k0 + brow) * H_ + n0 + bcol4];
        __syncthreads();
        As[(aseg * 4 + 0) * 132 + arow] = av.x;
        As[(aseg * 4 + 1) * 132 + arow] = av.y;
        As[(aseg * 4 + 2) * 132 + arow] = av.z;
        As[(aseg * 4 + 3) * 132 + arow] = av.w;
        *(float4*)&Bs[brow * 132 + bcol4] = bv;
        __syncthreads();
#pragma unroll
        for (int kk = 0; kk < 8; ++kk) {
            float a[8], b[8];
            float4 a0 = *(const float4*)&As[kk * 132 + ty * 8];
            float4 a1 = *(const float4*)&As[kk * 132 + ty * 8 + 4];
            float4 b0 = *(const float4*)&Bs[kk * 132 + tx * 8];
            float4 b1 = *(const float4*)&Bs[kk * 132 + tx * 8 + 4];
            a[0]=a0.x; a[1]=a0.y; a[2]=a0.z; a[3]=a0.w;
            a[4]=a1.x; a[5]=a1.y; a[6]=a1.z; a[7]=a1.w;
            b[0]=b0.x; b[1]=b0.y; b[2]=b0.z; b[3]=b0.w;
            b[4]=b1.x; b[5]=b1.y; b[6]=b1.z; b[7]=b1.w;
#pragma unroll
            for (int i = 0; i < 8; ++i)
#pragma unroll
                for (int j = 0; j < 8; ++j) acc[i][j] += a[i] * b[j];
        }
    }

#pragma unroll
    for (int j = 0; j < 8; ++j) {
        const int n = n0 + tx * 8 + j;
        const float bia = bias[n];
#pragma unroll
        for (int i = 0; i < 8; ++i) {
            const int m = m0 + ty * 8 + i;
            const int t = m & (T_ - 1);
            const int b = m >> 10;
            out[(size_t)(t * H_ + n) * B_ + b] = acc[i][j] + bia;
        }
    }
}

// =================================================================================
// Persistent recurrence kernel: 128 CTAs (4 batch-groups x 32 col-groups), 1/SM.
// CTA (bg, cg) owns batches [bg*16, bg*16+16) and h-columns [cg*16, cg*16+16).
// =================================================================================
#define NCTA 128
#define NB_CTA 16              // batches per CTA
#define NC_CTA 16              // h-columns per CTA (48 gate-cols incl. z,r,hcand)
#define HS_S 520               // h_s[bl*520 + k]; FMA loads bank = (8b + k)&31
#define WS_S 49                // w_s[k*49 + c], c in 0..47; bank spread 17*lane
#define SMEM_FLOATS (NB_CTA * HS_S + H_ * WS_S + 256 + 256)
#define SMEM_BYTES  (SMEM_FLOATS * 4)

__device__ __forceinline__ float sigmoidf_(float x) {
    return 1.0f / (1.0f + expf(-x));
}

// exchange-and-specialize butterfly stage: live register count N halves.
#define RSTAGE(arr, N, M, lane)                                              \
    {                                                                        \
        const bool hi_ = ((lane) & (M)) != 0;                                \
        _Pragma("unroll")                                                    \
        for (int i_ = 0; i_ < (N); ++i_) {                                   \
            float send_ = hi_ ? arr[i_] : arr[i_ + (N)];                     \
            float recv_ = __shfl_xor_sync(0xffffffffu, send_, (M));          \
            arr[i_] = (hi_ ? arr[i_ + (N)] : arr[i_]) + recv_;               \
        }                                                                    \
    }

// Stage this CTA's 16-batch h slice: 8192 floats = 2048 float4, 8 per thread,
// all LDGs issued before any STS (max MLP).
__device__ __forceinline__ void stage_h_(float* h_s, const float4* __restrict__ src, int tid) {
    float4 v[8];
#pragma unroll
    for (int u = 0; u < 8; ++u)
        v[u] = __ldcg(src + tid + u * 256);
#pragma unroll
    for (int u = 0; u < 8; ++u) {
        const int i = tid + u * 256;
        const int bl = i >> 7;               // 128 float4 per batch row
        const int k4 = (i & 127) << 2;
        *(float4*)&h_s[bl * HS_S + k4] = v[u];
    }
}

__global__ __launch_bounds__(256, 1) void gru_rec_kernel(
    const float* __restrict__ Wz, const float* __restrict__ Wr, const float* __restrict__ Wh,
    float* __restrict__ out)
{
    extern __shared__ float smem[];
    float* h_s  = smem;                        // NB_CTA * 520
    float* w_s  = h_s + NB_CTA * HS_S;         // H_ * 49
    float* z_s  = w_s + H_ * WS_S;             // 16 batches * 16 cols
    float* hk_s = z_s + 256;                   // 16 * 16

    const int tid  = (int)threadIdx.x;
    const int w    = tid >> 5;
    const int lane = tid & 31;
    const int bg   = (int)blockIdx.x >> 5;     // batch group 0..3
    const int cg   = (int)blockIdx.x & 31;     // col group 0..31
    const int col0 = cg * NC_CTA;              // first h-col
    const int bc0  = bg * NB_CTA;              // first batch

    const int bw = w >> 2;                     // warp batch tile 0..1 (8 batches)
    const int cw = w & 3;                      // warp col tile 0..3
    const int blbase = bw * 8;                 // local batch base of this warp

    // ---- one-time: stage 48 weight columns (16 z | 16 r | 16 h) ----
    for (int i = tid; i < H_ * 48; i += 256) {
        const int k = i / 48, c = i % 48;
        const float* W = (c < 16) ? Wz : (c < 32) ? Wr : Wh;
        w_s[k * WS_S + c] = W[(size_t)(I_ + k) * H_ + col0 + (c & 15)];
    }

    // ---- per-lane epilogue mappings ----
    // phase A: lane ends with acc{2l,2l+1}: c8 = l>>2, local batch pair 2(l&3)
    const int gcA   = cw * 8 + (lane >> 2);    // gate col 0..31 (0-15 z, 16-31 r)
    const int jA    = gcA & 15;                // h-col local
    const int blA   = blbase + 2 * (lane & 3); // local batch (even)
    const bool isZ  = gcA < 16;
    const float* xpA_base = isZ ? g_xz : g_xr;
    // phase B: lane ends with accB[l]: local batch = blbase + (l>>2), col = cw*4 + (l&3)
    const int blB = blbase + (lane >> 2);
    const int jB  = cw * 4 + (lane & 3);

#pragma unroll 1
    for (int t = 0; t < T_; ++t) {
        // ---- stage h slice (layout [local b][k]) ----
        __syncthreads();   // h_s free (covers w_s staging on iter 0)
        stage_h_(h_s, (const float4*)&g_h[t & 1][(size_t)bc0 * H_], tid);
        float2 xpA = __ldcg((const float2*)&xpA_base[((size_t)t * H_ + col0 + jA) * B_ + bc0 + blA]);
        __syncthreads();

        // ---- phase A: z,r dots; warp = 8 gate-cols x 8 batches, k-split 32 ----
        float acc[64];
#pragma unroll
        for (int i = 0; i < 64; ++i) acc[i] = 0.f;
#pragma unroll 4
        for (int it = 0; it < 16; ++it) {
            const int k = lane + (it << 5);
            float wv[8], hv[8];
#pragma unroll
            for (int c = 0; c < 8; ++c) wv[c] = w_s[k * WS_S + cw * 8 + c];
#pragma unroll
            for (int b = 0; b < 8; ++b) hv[b] = h_s[(blbase + b) * HS_S + k];
#pragma unroll
            for (int c = 0; c < 8; ++c)
#pragma unroll
                for (int b = 0; b < 8; ++b) acc[c * 8 + b] += wv[c] * hv[b];
        }
        RSTAGE(acc, 32, 16, lane)
        RSTAGE(acc, 16,  8, lane)
        RSTAGE(acc,  8,  4, lane)
        RSTAGE(acc,  4,  2, lane)
        RSTAGE(acc,  2,  1, lane)

        if (isZ) {
            const float z0 = sigmoidf_(xpA.x + acc[0]);
            const float z1 = sigmoidf_(xpA.y + acc[1]);
            z_s[blA * 16 + jA]       = z0;
            z_s[(blA + 1) * 16 + jA] = z1;
        } else {
            const float r0 = sigmoidf_(xpA.x + acc[0]);
            const float r1 = sigmoidf_(xpA.y + acc[1]);
            const float h0 = h_s[blA * HS_S + col0 + jA];
            const float h1 = h_s[(blA + 1) * HS_S + col0 + jA];
            hk_s[blA * 16 + jA]       = h0;
            hk_s[(blA + 1) * 16 + jA] = h1;
            __stcg(&g_rh[(size_t)(bc0 + blA) * H_ + col0 + jA], r0 * h0);
            __stcg(&g_rh[(size_t)(bc0 + blA + 1) * H_ + col0 + jA], r1 * h1);
        }
        grid_sync_(NCTA);

        // ---- stage r*h slice ----
        stage_h_(h_s, (const float4*)&g_rh[(size_t)bc0 * H_], tid);
        float xpB = __ldcg(&g_xh[((size_t)t * H_ + col0 + jB) * B_ + bc0 + blB]);
        __syncthreads();

        // ---- phase B: candidate dots; warp = 4 cols x 8 batches ----
        float accB[32];
#pragma unroll
        for (int i = 0; i < 32; ++i) accB[i] = 0.f;
#pragma unroll 4
        for (int it = 0; it < 16; ++it) {
            const int k = lane + (it << 5);
            float wv[4], hv[8];
#pragma unroll
            for (int c = 0; c < 4; ++c) wv[c] = w_s[k * WS_S + 32 + cw * 4 + c];
#pragma unroll
            for (int b = 0; b < 8; ++b) hv[b] = h_s[(blbase + b) * HS_S + k];
#pragma unroll
            for (int b = 0; b < 8; ++b)
#pragma unroll
                for (int c = 0; c < 4; ++c) accB[b * 4 + c] += wv[c] * hv[b];
        }
        RSTAGE(accB, 16, 16, lane)
        RSTAGE(accB,  8,  8, lane)
        RSTAGE(accB,  4,  4, lane)
        RSTAGE(accB,  2,  2, lane)
        RSTAGE(accB,  1,  1, lane)

        {
            const float z    = z_s[blB * 16 + jB];
            const float hold = hk_s[blB * 16 + jB];
            const float ht = tanhf(xpB + accB[0]);
            const float hn = fmaf(z, ht - hold, hold);
            const int gb = bc0 + blB;
            out[(size_t)gb * T_ * H_ + (size_t)t * H_ + col0 + jB] = hn;
            __stcg(&g_h[(t + 1) & 1][(size_t)gb * H_ + col0 + jB], hn);
            if (t == T_ - 1)
                out[(size_t)B_ * T_ * H_ + (size_t)gb * H_ + col0 + jB] = hn;
        }
        grid_sync_(NCTA);
    }
}

// =================================================================================
extern "C" void kernel_launch(void* const* d_in, const int* in_sizes, int n_in,
                              void* d_out, int out_size) {
    const float* xs = (const float*)d_in[0];
    const float* Wz = (const float*)d_in[1];
    const float* bz = (const float*)d_in[2];
    const float* Wr = (const float*)d_in[3];
    const float* br = (const float*)d_in[4];
    const float* Wh = (const float*)d_in[5];
    const float* bh = (const float*)d_in[6];
    float* out = (float*)d_out;

    cudaFuncSetAttribute(gru_rec_kernel,
                         cudaFuncAttributeMaxDynamicSharedMemorySize, SMEM_BYTES);

    gru_init_kernel<<<(H_ * B_ + 511) / 512, 512>>>();

    dim3 pg(T_ * B_ / 128, H_ / 128, 3);
    gru_proj_kernel<<<pg, 256>>>(xs, Wz, Wr, Wh, bz, br, bh);

    gru_rec_kernel<<<NCTA, 256, SMEM_BYTES>>>(Wz, Wr, Wh, out);
}

// round 6
// speedup vs baseline: 2.2370x; 1.0158x over previous
#include <cuda_runtime.h>
#include <cstdint>

#define B_ 64
#define T_ 1024
#define I_ 256
#define H_ 512

// ---------------- static device scratch (no dynamic allocation) ----------------
// Projections stored transposed: [t][j][b]  -> index (t*H_ + j)*B_ + b
__device__ float g_xz[(size_t)T_ * H_ * B_];
__device__ float g_xr[(size_t)T_ * H_ * B_];
__device__ float g_xh[(size_t)T_ * H_ * B_];
// Hidden state double buffer + r*h exchange buffer, layout [b][j]
__device__ float g_h[2][B_ * H_];
__device__ float g_rh[B_ * H_];
// Per-batch-group barrier state: 4 independent slots, 128B apart
struct __align__(128) BarSlot { unsigned count; unsigned gen; unsigned pad[30]; };
__device__ BarSlot g_bar[4];

// ---------------- per-batch-group barrier (round-3 proven protocol, scoped) ----
__device__ __forceinline__ void group_sync_(int bg) {
    __threadfence();
    __syncthreads();
    if (threadIdx.x == 0) {
        volatile unsigned* genp = &g_bar[bg].gen;
        unsigned gen = *genp;
        if (atomicAdd(&g_bar[bg].count, 1u) == 31u) {
            atomicExch(&g_bar[bg].count, 0u);
            __threadfence();
            atomicExch((unsigned*)&g_bar[bg].gen, gen + 1u);
        } else {
            while (*genp == gen) {}
        }
    }
    __syncthreads();
    __threadfence();
}

// =================================================================================
__global__ void gru_init_kernel() {
    int idx = blockIdx.x * blockDim.x + threadIdx.x;
    if (idx < H_ * B_) {
        g_h[0][idx] = 0.f;
        g_h[1][idx] = 0.f;
    }
    if (idx < 4) {
        g_bar[idx].count = 0u;
        g_bar[idx].gen   = 0u;
    }
}

// =================================================================================
// Projection GEMM:  out_g[t][n][b] = xs[b][t][:] . Wg[0:I][n] + bias_g[n]
// =================================================================================
__global__ __launch_bounds__(256) void gru_proj_kernel(
    const float* __restrict__ xs,
    const float* __restrict__ Wz, const float* __restrict__ Wr, const float* __restrict__ Wh,
    const float* __restrict__ bz, const float* __restrict__ br, const float* __restrict__ bh)
{
    __shared__ float As[8 * 132];
    __shared__ float Bs[8 * 132];

    const int g = blockIdx.z;
    const float* W    = (g == 0) ? Wz : (g == 1) ? Wr : Wh;
    const float* bias = (g == 0) ? bz : (g == 1) ? br : bh;
    float*       out  = (g == 0) ? g_xz : (g == 1) ? g_xr : g_xh;

    const int m0 = blockIdx.x * 128;
    const int n0 = blockIdx.y * 128;
    const int tid = (int)threadIdx.x;

    const int tx = tid & 15;
    const int ty = tid >> 4;

    const int arow = tid >> 1, aseg = tid & 1;
    const int brow = tid >> 5, bcol4 = (tid & 31) * 4;

    float acc[8][8];
#pragma unroll
    for (int i = 0; i < 8; ++i)
#pragma unroll
        for (int j = 0; j < 8; ++j) acc[i][j] = 0.f;

    for (int k0 = 0; k0 < I_; k0 += 8) {
        float4 av = *(const float4*)&xs[(size_t)(m0 + arow) * I_ + k0 + aseg * 4];
        float4 bv = *(const float4*)&W[(size_t)(k0 + brow) * H_ + n0 + bcol4];
        __syncthreads();
        As[(aseg * 4 + 0) * 132 + arow] = av.x;
        As[(aseg * 4 + 1) * 132 + arow] = av.y;
        As[(aseg * 4 + 2) * 132 + arow] = av.z;
        As[(aseg * 4 + 3) * 132 + arow] = av.w;
        *(float4*)&Bs[brow * 132 + bcol4] = bv;
        __syncthreads();
#pragma unroll
        for (int kk = 0; kk < 8; ++kk) {
            float a[8], b[8];
            float4 a0 = *(const float4*)&As[kk * 132 + ty * 8];
            float4 a1 = *(const float4*)&As[kk * 132 + ty * 8 + 4];
            float4 b0 = *(const float4*)&Bs[kk * 132 + tx * 8];
            float4 b1 = *(const float4*)&Bs[kk * 132 + tx * 8 + 4];
            a[0]=a0.x; a[1]=a0.y; a[2]=a0.z; a[3]=a0.w;
            a[4]=a1.x; a[5]=a1.y; a[6]=a1.z; a[7]=a1.w;
            b[0]=b0.x; b[1]=b0.y; b[2]=b0.z; b[3]=b0.w;
            b[4]=b1.x; b[5]=b1.y; b[6]=b1.z; b[7]=b1.w;
#pragma unroll
            for (int i = 0; i < 8; ++i)
#pragma unroll
                for (int j = 0; j < 8; ++j) acc[i][j] += a[i] * b[j];
        }
    }

#pragma unroll
    for (int j = 0; j < 8; ++j) {
        const int n = n0 + tx * 8 + j;
        const float bia = bias[n];
#pragma unroll
        for (int i = 0; i < 8; ++i) {
            const int m = m0 + ty * 8 + i;
            const int t = m & (T_ - 1);
            const int b = m >> 10;
            out[(size_t)(t * H_ + n) * B_ + b] = acc[i][j] + bia;
        }
    }
}

// =================================================================================
// Persistent recurrence kernel: 128 CTAs (4 batch-groups x 32 col-groups), 1/SM.
// CTA (bg, cg) owns batches [bg*16, bg*16+16) and h-columns [cg*16, cg*16+16).
// Synchronization is per batch group (32 CTAs) — groups never share data.
// =================================================================================
#define NB_CTA 16              // batches per CTA
#define NC_CTA 16              // h-columns per CTA (48 gate-cols incl. z,r,hcand)
#define HS_S 520               // h_s[bl*520 + k]; FMA loads bank = (8b + k)&31
#define WS_S 49                // w_s[k*49 + c], c in 0..47
#define SMEM_FLOATS (NB_CTA * HS_S + H_ * WS_S + 256 + 256)
#define SMEM_BYTES  (SMEM_FLOATS * 4)

__device__ __forceinline__ float sigmoidf_(float x) {
    return 1.0f / (1.0f + expf(-x));
}

// exchange-and-specialize butterfly stage: live register count N halves.
#define RSTAGE(arr, N, M, lane)                                              \
    {                                                                        \
        const bool hi_ = ((lane) & (M)) != 0;                                \
        _Pragma("unroll")                                                    \
        for (int i_ = 0; i_ < (N); ++i_) {                                   \
            float send_ = hi_ ? arr[i_] : arr[i_ + (N)];                     \
            float recv_ = __shfl_xor_sync(0xffffffffu, send_, (M));          \
            arr[i_] = (hi_ ? arr[i_ + (N)] : arr[i_]) + recv_;               \
        }                                                                    \
    }

// Stage this CTA's 16-batch slice: 8192 floats = 2048 float4, 8 per thread,
// all LDGs issued before any STS (max MLP).
__device__ __forceinline__ void stage_h_(float* h_s, const float4* __restrict__ src, int tid) {
    float4 v[8];
#pragma unroll
    for (int u = 0; u < 8; ++u)
        v[u] = __ldcg(src + tid + u * 256);
#pragma unroll
    for (int u = 0; u < 8; ++u) {
        const int i = tid + u * 256;
        const int bl = i >> 7;               // 128 float4 per batch row
        const int k4 = (i & 127) << 2;
        *(float4*)&h_s[bl * HS_S + k4] = v[u];
    }
}

__global__ __launch_bounds__(256, 1) void gru_rec_kernel(
    const float* __restrict__ Wz, const float* __restrict__ Wr, const float* __restrict__ Wh,
    float* __restrict__ out)
{
    extern __shared__ float smem[];
    float* h_s  = smem;                        // NB_CTA * 520
    float* w_s  = h_s + NB_CTA * HS_S;         // H_ * 49
    float* z_s  = w_s + H_ * WS_S;             // 16 batches * 16 cols
    float* hk_s = z_s + 256;                   // 16 * 16

    const int tid  = (int)threadIdx.x;
    const int w    = tid >> 5;
    const int lane = tid & 31;
    const int bg   = (int)blockIdx.x >> 5;     // batch group 0..3
    const int cg   = (int)blockIdx.x & 31;     // col group 0..31
    const int col0 = cg * NC_CTA;              // first h-col
    const int bc0  = bg * NB_CTA;              // first batch

    const int bw = w >> 2;                     // warp batch tile 0..1 (8 batches)
    const int cw = w & 3;                      // warp col tile 0..3
    const int blbase = bw * 8;                 // local batch base of this warp

    // ---- one-time: stage 48 weight columns (16 z | 16 r | 16 h) ----
    for (int i = tid; i < H_ * 48; i += 256) {
        const int k = i / 48, c = i % 48;
        const float* W = (c < 16) ? Wz : (c < 32) ? Wr : Wh;
        w_s[k * WS_S + c] = W[(size_t)(I_ + k) * H_ + col0 + (c & 15)];
    }

    // ---- per-lane epilogue mappings ----
    const int gcA   = cw * 8 + (lane >> 2);    // gate col 0..31 (0-15 z, 16-31 r)
    const int jA    = gcA & 15;                // h-col local
    const int blA   = blbase + 2 * (lane & 3); // local batch (even)
    const bool isZ  = gcA < 16;
    const float* xpA_base = isZ ? g_xz : g_xr;
    const int blB = blbase + (lane >> 2);
    const int jB  = cw * 4 + (lane & 3);

#pragma unroll 1
    for (int t = 0; t < T_; ++t) {
        // ---- stage h slice (layout [local b][k]) ----
        __syncthreads();   // h_s free (covers w_s staging on iter 0)
        stage_h_(h_s, (const float4*)&g_h[t & 1][(size_t)bc0 * H_], tid);
        float2 xpA = __ldcg((const float2*)&xpA_base[((size_t)t * H_ + col0 + jA) * B_ + bc0 + blA]);
        __syncthreads();

        // ---- phase A: z,r dots; warp = 8 gate-cols x 8 batches, k-split 32 ----
        float acc[64];
#pragma unroll
        for (int i = 0; i < 64; ++i) acc[i] = 0.f;
#pragma unroll 4
        for (int it = 0; it < 16; ++it) {
            const int k = lane + (it << 5);
            float wv[8], hv[8];
#pragma unroll
            for (int c = 0; c < 8; ++c) wv[c] = w_s[k * WS_S + cw * 8 + c];
#pragma unroll
            for (int b = 0; b < 8; ++b) hv[b] = h_s[(blbase + b) * HS_S + k];
#pragma unroll
            for (int c = 0; c < 8; ++c)
#pragma unroll
                for (int b = 0; b < 8; ++b) acc[c * 8 + b] += wv[c] * hv[b];
        }
        RSTAGE(acc, 32, 16, lane)
        RSTAGE(acc, 16,  8, lane)
        RSTAGE(acc,  8,  4, lane)
        RSTAGE(acc,  4,  2, lane)
        RSTAGE(acc,  2,  1, lane)

        if (isZ) {
            const float z0 = sigmoidf_(xpA.x + acc[0]);
            const float z1 = sigmoidf_(xpA.y + acc[1]);
            z_s[blA * 16 + jA]       = z0;
            z_s[(blA + 1) * 16 + jA] = z1;
        } else {
            const float r0 = sigmoidf_(xpA.x + acc[0]);
            const float r1 = sigmoidf_(xpA.y + acc[1]);
            const float h0 = h_s[blA * HS_S + col0 + jA];
            const float h1 = h_s[(blA + 1) * HS_S + col0 + jA];
            hk_s[blA * 16 + jA]       = h0;
            hk_s[(blA + 1) * 16 + jA] = h1;
            __stcg(&g_rh[(size_t)(bc0 + blA) * H_ + col0 + jA], r0 * h0);
            __stcg(&g_rh[(size_t)(bc0 + blA + 1) * H_ + col0 + jA], r1 * h1);
        }
        group_sync_(bg);

        // ---- stage r*h slice ----
        stage_h_(h_s, (const float4*)&g_rh[(size_t)bc0 * H_], tid);
        float xpB = __ldcg(&g_xh[((size_t)t * H_ + col0 + jB) * B_ + bc0 + blB]);
        __syncthreads();

        // ---- phase B: candidate dots; warp = 4 cols x 8 batches ----
        float accB[32];
#pragma unroll
        for (int i = 0; i < 32; ++i) accB[i] = 0.f;
#pragma unroll 4
        for (int it = 0; it < 16; ++it) {
            const int k = lane + (it << 5);
            float wv[4], hv[8];
#pragma unroll
            for (int c = 0; c < 4; ++c) wv[c] = w_s[k * WS_S + 32 + cw * 4 + c];
#pragma unroll
            for (int b = 0; b < 8; ++b) hv[b] = h_s[(blbase + b) * HS_S + k];
#pragma unroll
            for (int b = 0; b < 8; ++b)
#pragma unroll
                for (int c = 0; c < 4; ++c) accB[b * 4 + c] += wv[c] * hv[b];
        }
        RSTAGE(accB, 16, 16, lane)
        RSTAGE(accB,  8,  8, lane)
        RSTAGE(accB,  4,  4, lane)
        RSTAGE(accB,  2,  2, lane)
        RSTAGE(accB,  1,  1, lane)

        {
            const float z    = z_s[blB * 16 + jB];
            const float hold = hk_s[blB * 16 + jB];
            const float ht = tanhf(xpB + accB[0]);
            const float hn = fmaf(z, ht - hold, hold);
            const int gb = bc0 + blB;
            out[(size_t)gb * T_ * H_ + (size_t)t * H_ + col0 + jB] = hn;
            __stcg(&g_h[(t + 1) & 1][(size_t)gb * H_ + col0 + jB], hn);
            if (t == T_ - 1)
                out[(size_t)B_ * T_ * H_ + (size_t)gb * H_ + col0 + jB] = hn;
        }
        group_sync_(bg);
    }
}

// =================================================================================
extern "C" void kernel_launch(void* const* d_in, const int* in_sizes, int n_in,
                              void* d_out, int out_size) {
    const float* xs = (const float*)d_in[0];
    const float* Wz = (const float*)d_in[1];
    const float* bz = (const float*)d_in[2];
    const float* Wr = (const float*)d_in[3];
    const float* br = (const float*)d_in[4];
    const float* Wh = (const float*)d_in[5];
    const float* bh = (const float*)d_in[6];
    float* out = (float*)d_out;

    cudaFuncSetAttribute(gru_rec_kernel,
                         cudaFuncAttributeMaxDynamicSharedMemorySize, SMEM_BYTES);

    gru_init_kernel<<<(H_ * B_ + 511) / 512, 512>>>();

    dim3 pg(T_ * B_ / 128, H_ / 128, 3);
    gru_proj_kernel<<<pg, 256>>>(xs, Wz, Wr, Wh, bz, br, bh);

    gru_rec_kernel<<<128, 256, SMEM_BYTES>>>(Wz, Wr, Wh, out);
}

// round 8
// speedup vs baseline: 2.3576x; 1.0539x over previous
#include <cuda_runtime.h>
#include <cstdint>

#define B_ 64
#define T_ 1024
#define I_ 256
#define H_ 512

typedef unsigned long long u64;

// ---------------- packed f32x2 helpers (sm_103a) ----------------
__device__ __forceinline__ u64 pack2(float lo, float hi) {
    u64 r; asm("mov.b64 %0, {%1, %2};" : "=l"(r) : "f"(lo), "f"(hi)); return r;
}
__device__ __forceinline__ u64 fma2(u64 a, u64 b, u64 c) {
    u64 d; asm("fma.rn.f32x2 %0, %1, %2, %3;" : "=l"(d) : "l"(a), "l"(b), "l"(c)); return d;
}
__device__ __forceinline__ u64 add2(u64 a, u64 b) {
    u64 d; asm("add.rn.f32x2 %0, %1, %2;" : "=l"(d) : "l"(a), "l"(b)); return d;
}
__device__ __forceinline__ float2 unpack2(u64 v) {
    float2 r; asm("mov.b64 {%0, %1}, %2;" : "=f"(r.x), "=f"(r.y) : "l"(v)); return r;
}

// ---------------- static device scratch (no dynamic allocation) ----------------
// Projections stored transposed: [t][j][b]  -> index (t*H_ + j)*B_ + b
__device__ float g_xz[(size_t)T_ * H_ * B_];
__device__ float g_xr[(size_t)T_ * H_ * B_];
__device__ float g_xh[(size_t)T_ * H_ * B_];
// Hidden state double buffer + r*h exchange buffer, layout [b][j]
__device__ float g_h[2][B_ * H_];
__device__ float g_rh[B_ * H_];
// Per-batch-group barrier state: 4 independent slots, 128B apart.
// Statically zero-initialized; count self-resets; gen is monotone (replay-safe).
struct __align__(128) BarSlot { unsigned count; unsigned gen; unsigned pad[30]; };
__device__ BarSlot g_bar[4];

// ---------------- per-batch-group barrier (proven protocol, scoped) ----------
__device__ __forceinline__ void group_sync_(int bg) {
    __threadfence();
    __syncthreads();
    if (threadIdx.x == 0) {
        volatile unsigned* genp = &g_bar[bg].gen;
        unsigned gen = *genp;
        if (atomicAdd(&g_bar[bg].count, 1u) == 31u) {
            atomicExch(&g_bar[bg].count, 0u);
            __threadfence();
            atomicExch((unsigned*)&g_bar[bg].gen, gen + 1u);
        } else {
            while (*genp == gen) {}
        }
    }
    __syncthreads();
    __threadfence();
}

// =================================================================================
// Projection GEMM:  out_g[t][n][b] = xs[b][t][:] . Wg[0:I][n] + bias_g[n]
// f32x2-packed microtile: 8 rows x 4 col-pairs per thread.
// =================================================================================
__global__ __launch_bounds__(256) void gru_proj_kernel(
    const float* __restrict__ xs,
    const float* __restrict__ Wz, const float* __restrict__ Wr, const float* __restrict__ Wh,
    const float* __restrict__ bz, const float* __restrict__ br, const float* __restrict__ bh)
{
    __shared__ float As[8 * 132];
    __shared__ float Bs[8 * 132];

    const int g = blockIdx.z;
    const float* W    = (g == 0) ? Wz : (g == 1) ? Wr : Wh;
    const float* bias = (g == 0) ? bz : (g == 1) ? br : bh;
    float*       out  = (g == 0) ? g_xz : (g == 1) ? g_xr : g_xh;

    const int m0 = blockIdx.x * 128;
    const int n0 = blockIdx.y * 128;
    const int tid = (int)threadIdx.x;

    const int tx = tid & 15;
    const int ty = tid >> 4;

    const int arow = tid >> 1, aseg = tid & 1;
    const int brow = tid >> 5, bcol4 = (tid & 31) * 4;

    u64 acc2[8][4];
#pragma unroll
    for (int i = 0; i < 8; ++i)
#pragma unroll
        for (int j = 0; j < 4; ++j) acc2[i][j] = 0ull;

    for (int k0 = 0; k0 < I_; k0 += 8) {
        float4 av = *(const float4*)&xs[(size_t)(m0 + arow) * I_ + k0 + aseg * 4];
        float4 bv = *(const float4*)&W[(size_t)(k0 + brow) * H_ + n0 + bcol4];
        __syncthreads();
        As[(aseg * 4 + 0) * 132 + arow] = av.x;
        As[(aseg * 4 + 1) * 132 + arow] = av.y;
        As[(aseg * 4 + 2) * 132 + arow] = av.z;
        As[(aseg * 4 + 3) * 132 + arow] = av.w;
        *(float4*)&Bs[brow * 132 + bcol4] = bv;
        __syncthreads();
#pragma unroll
        for (int kk = 0; kk < 8; ++kk) {
            float a[8];
            float4 a0 = *(const float4*)&As[kk * 132 + ty * 8];
            float4 a1 = *(const float4*)&As[kk * 132 + ty * 8 + 4];
            float4 b0 = *(const float4*)&Bs[kk * 132 + tx * 8];
            float4 b1 = *(const float4*)&Bs[kk * 132 + tx * 8 + 4];
            a[0]=a0.x; a[1]=a0.y; a[2]=a0.z; a[3]=a0.w;
            a[4]=a1.x; a[5]=a1.y; a[6]=a1.z; a[7]=a1.w;
            u64 bp[4];
            bp[0] = pack2(b0.x, b0.y); bp[1] = pack2(b0.z, b0.w);
            bp[2] = pack2(b1.x, b1.y); bp[3] = pack2(b1.z, b1.w);
#pragma unroll
            for (int i = 0; i < 8; ++i) {
                u64 ap = pack2(a[i], a[i]);
#pragma unroll
                for (int j = 0; j < 4; ++j) acc2[i][j] = fma2(ap, bp[j], acc2[i][j]);
            }
        }
    }

#pragma unroll
    for (int j = 0; j < 4; ++j) {
        const int n = n0 + tx * 8 + 2 * j;
        const float bi0 = bias[n], bi1 = bias[n + 1];
#pragma unroll
        for (int i = 0; i < 8; ++i) {
            const int m = m0 + ty * 8 + i;
            const int t = m & (T_ - 1);
            const int b = m >> 10;
            float2 v = unpack2(acc2[i][j]);
            out[(size_t)(t * H_ + n) * B_ + b]     = v.x + bi0;
            out[(size_t)(t * H_ + n + 1) * B_ + b] = v.y + bi1;
        }
    }
}

// =================================================================================
// Persistent recurrence kernel: 128 CTAs (4 batch-groups x 32 col-groups), 1/SM.
// CTA (bg, cg) owns batches [bg*16, bg*16+16) and h-columns [cg*16, cg*16+16).
// =================================================================================
#define NB_CTA 16
#define NC_CTA 16
#define HS_S 520               // h_s[bl*520 + k]; scalar loads bank (8b + lane)
#define WS_S 52                // w_s[k*52 + c]; 16B aligned, quad = (13k + c/4)&7
#define SMEM_FLOATS (NB_CTA * HS_S + H_ * WS_S + 256 + 256)
#define SMEM_BYTES  (SMEM_FLOATS * 4)

__device__ __forceinline__ float sigmoidf_(float x) {
    return 1.0f / (1.0f + expf(-x));
}

// exchange-and-specialize butterfly stage on packed u64 accumulators.
#define RSTAGE64(arr, N, M, lane)                                            \
    {                                                                        \
        const bool hi_ = ((lane) & (M)) != 0;                                \
        _Pragma("unroll")                                                    \
        for (int i_ = 0; i_ < (N); ++i_) {                                   \
            u64 send_ = hi_ ? arr[i_] : arr[i_ + (N)];                       \
            u64 recv_ = __shfl_xor_sync(0xffffffffu, send_, (M));            \
            u64 keep_ = hi_ ? arr[i_ + (N)] : arr[i_];                       \
            arr[i_] = add2(keep_, recv_);                                    \
        }                                                                    \
    }

// Stage this CTA's 16-batch slice: 2048 float4, 8 per thread, LDG-batched.
__device__ __forceinline__ void stage_h_(float* h_s, const float4* __restrict__ src, int tid) {
    float4 v[8];
#pragma unroll
    for (int u = 0; u < 8; ++u)
        v[u] = __ldcg(src + tid + u * 256);
#pragma unroll
    for (int u = 0; u < 8; ++u) {
        const int i = tid + u * 256;
        const int bl = i >> 7;
        const int k4 = (i & 127) << 2;
        *(float4*)&h_s[bl * HS_S + k4] = v[u];
    }
}

__global__ __launch_bounds__(256, 1) void gru_rec_kernel(
    const float* __restrict__ Wz, const float* __restrict__ Wr, const float* __restrict__ Wh,
    float* __restrict__ out)
{
    extern __shared__ float smem[];
    float* h_s  = smem;                        // NB_CTA * 520
    float* w_s  = h_s + NB_CTA * HS_S;         // H_ * 52
    float* z_s  = w_s + H_ * WS_S;             // 16 x 16
    float* hk_s = z_s + 256;                   // 16 x 16

    const int tid  = (int)threadIdx.x;
    const int w    = tid >> 5;
    const int lane = tid & 31;
    const int bg   = (int)blockIdx.x >> 5;
    const int cg   = (int)blockIdx.x & 31;
    const int col0 = cg * NC_CTA;
    const int bc0  = bg * NB_CTA;

    const int bw = w >> 2;
    const int cw = w & 3;
    const int blbase = bw * 8;

    // ---- one-time: stage 48 weight columns (16 z | 16 r | 16 h), slots 0..47 ----
    for (int i = tid; i < H_ * 48; i += 256) {
        const int k = i / 48, c = i % 48;
        const float* W = (c < 16) ? Wz : (c < 32) ? Wr : Wh;
        w_s[k * WS_S + c] = W[(size_t)(I_ + k) * H_ + col0 + (c & 15)];
    }

    // ---- per-lane epilogue mappings ----
    // phase A (packed idx = c*4+p, 5-stage cascade -> lane l holds idx l):
    const int gcA   = cw * 8 + (lane >> 2);    // gate col 0..31 (0-15 z, 16-31 r)
    const int jA    = gcA & 15;
    const int blA   = blbase + 2 * (lane & 3); // batch pair (blA, blA+1)
    const bool isZ  = gcA < 16;
    const float* xpA_base = isZ ? g_xz : g_xr;
    // phase B (packed idx = p*4+c, 4-stage cascade -> lane l holds idx l>>1;
    //          final mask-1 packed ADD completes the k-sum, half select = l&1):
    const int blB = blbase + 2 * (lane >> 3) + (lane & 1);
    const int jB  = cw * 4 + ((lane >> 1) & 3);

#pragma unroll 1
    for (int t = 0; t < T_; ++t) {
        // ---- stage h slice (layout [local b][k]); t==0: h = 0 ----
        __syncthreads();   // h_s free (covers w_s staging on iter 0)
        if (t == 0) {
#pragma unroll
            for (int u = 0; u < 8; ++u) {
                const int i = tid + u * 256;
                const int bl = i >> 7, k4 = (i & 127) << 2;
                *(float4*)&h_s[bl * HS_S + k4] = make_float4(0.f, 0.f, 0.f, 0.f);
            }
        } else {
            stage_h_(h_s, (const float4*)&g_h[t & 1][(size_t)bc0 * H_], tid);
        }
        float2 xpA = __ldcg((const float2*)&xpA_base[((size_t)t * H_ + col0 + jA) * B_ + bc0 + blA]);
        __syncthreads();

        // ---- phase A: z,r dots; warp = 8 gate-cols x 4 batch-pairs, k-split 32 ----
        u64 acc2[32];                          // idx = c*4 + p
#pragma unroll
        for (int i = 0; i < 32; ++i) acc2[i] = 0ull;
#pragma unroll 4
        for (int it = 0; it < 16; ++it) {
            const int k = lane + (it << 5);
            float4 w0 = *(const float4*)&w_s[k * WS_S + cw * 8];
            float4 w1 = *(const float4*)&w_s[k * WS_S + cw * 8 + 4];
            float hv[8];
#pragma unroll
            for (int b = 0; b < 8; ++b) hv[b] = h_s[(blbase + b) * HS_S + k];
            u64 hp[4];
#pragma unroll
            for (int p = 0; p < 4; ++p) hp[p] = pack2(hv[2 * p], hv[2 * p + 1]);
            float wv[8];
            wv[0]=w0.x; wv[1]=w0.y; wv[2]=w0.z; wv[3]=w0.w;
            wv[4]=w1.x; wv[5]=w1.y; wv[6]=w1.z; wv[7]=w1.w;
#pragma unroll
            for (int c = 0; c < 8; ++c) {
                u64 wp = pack2(wv[c], wv[c]);
#pragma unroll
                for (int p = 0; p < 4; ++p)
                    acc2[c * 4 + p] = fma2(wp, hp[p], acc2[c * 4 + p]);
            }
        }
        RSTAGE64(acc2, 16, 16, lane)
        RSTAGE64(acc2,  8,  8, lane)
        RSTAGE64(acc2,  4,  4, lane)
        RSTAGE64(acc2,  2,  2, lane)
        RSTAGE64(acc2,  1,  1, lane)

        {
            float2 dot = unpack2(acc2[0]);     // batches blA, blA+1 of gate col gcA
            if (isZ) {
                const float z0 = sigmoidf_(xpA.x + dot.x);
                const float z1 = sigmoidf_(xpA.y + dot.y);
                z_s[blA * 16 + jA]       = z0;
                z_s[(blA + 1) * 16 + jA] = z1;
            } else {
                const float r0 = sigmoidf_(xpA.x + dot.x);
                const float r1 = sigmoidf_(xpA.y + dot.y);
                const float h0 = h_s[blA * HS_S + col0 + jA];
                const float h1 = h_s[(blA + 1) * HS_S + col0 + jA];
                hk_s[blA * 16 + jA]       = h0;
                hk_s[(blA + 1) * 16 + jA] = h1;
                __stcg(&g_rh[(size_t)(bc0 + blA) * H_ + col0 + jA], r0 * h0);
                __stcg(&g_rh[(size_t)(bc0 + blA + 1) * H_ + col0 + jA], r1 * h1);
            }
        }
        group_sync_(bg);

        // ---- stage r*h slice ----
        stage_h_(h_s, (const float4*)&g_rh[(size_t)bc0 * H_], tid);
        float xpB = __ldcg(&g_xh[((size_t)t * H_ + col0 + jB) * B_ + bc0 + blB]);
        __syncthreads();

        // ---- phase B: candidate dots; warp = 4 cols x 4 batch-pairs ----
        u64 acc2B[16];                         // idx = p*4 + c
#pragma unroll
        for (int i = 0; i < 16; ++i) acc2B[i] = 0ull;
#pragma unroll 4
        for (int it = 0; it < 16; ++it) {
            const int k = lane + (it << 5);
            float4 wB = *(const float4*)&w_s[k * WS_S + 32 + cw * 4];
            float hv[8];
#pragma unroll
            for (int b = 0; b < 8; ++b) hv[b] = h_s[(blbase + b) * HS_S + k];
            u64 hp[4];
#pragma unroll
            for (int p = 0; p < 4; ++p) hp[p] = pack2(hv[2 * p], hv[2 * p + 1]);
            u64 wp[4];
            wp[0] = pack2(wB.x, wB.x); wp[1] = pack2(wB.y, wB.y);
            wp[2] = pack2(wB.z, wB.z); wp[3] = pack2(wB.w, wB.w);
#pragma unroll
            for (int p = 0; p < 4; ++p)
#pragma unroll
                for (int c = 0; c < 4; ++c)
                    acc2B[p * 4 + c] = fma2(wp[c], hp[p], acc2B[p * 4 + c]);
        }
        RSTAGE64(acc2B, 8, 16, lane)
        RSTAGE64(acc2B, 4,  8, lane)
        RSTAGE64(acc2B, 2,  4, lane)
        RSTAGE64(acc2B, 1,  2, lane)
        // final mask-1 exchange: combine complementary k-parity partials (both
        // lanes of each pair end with the FULL packed sum, then extract halves)
        acc2B[0] = add2(acc2B[0], __shfl_xor_sync(0xffffffffu, acc2B[0], 1));

        {
            float2 pair = unpack2(acc2B[0]);   // batches 2p, 2p+1 of col jB
            const float cand = (lane & 1) ? pair.y : pair.x;
            const float z    = z_s[blB * 16 + jB];
            const float hold = hk_s[blB * 16 + jB];
            const float ht = tanhf(xpB + cand);
            const float hn = fmaf(z, ht - hold, hold);
            const int gb = bc0 + blB;
            out[(size_t)gb * T_ * H_ + (size_t)t * H_ + col0 + jB] = hn;
            __stcg(&g_h[(t + 1) & 1][(size_t)gb * H_ + col0 + jB], hn);
            if (t == T_ - 1)
                out[(size_t)B_ * T_ * H_ + (size_t)gb * H_ + col0 + jB] = hn;
        }
        group_sync_(bg);
    }
}

// =================================================================================
extern "C" void kernel_launch(void* const* d_in, const int* in_sizes, int n_in,
                              void* d_out, int out_size) {
    const float* xs = (const float*)d_in[0];
    const float* Wz = (const float*)d_in[1];
    const float* bz = (const float*)d_in[2];
    const float* Wr = (const float*)d_in[3];
    const float* br = (const float*)d_in[4];
    const float* Wh = (const float*)d_in[5];
    const float* bh = (const float*)d_in[6];
    float* out = (float*)d_out;

    cudaFuncSetAttribute(gru_rec_kernel,
                         cudaFuncAttributeMaxDynamicSharedMemorySize, SMEM_BYTES);

    dim3 pg(T_ * B_ / 128, H_ / 128, 3);
    gru_proj_kernel<<<pg, 256>>>(xs, Wz, Wr, Wh, bz, br, bh);

    gru_rec_kernel<<<128, 256, SMEM_BYTES>>>(Wz, Wr, Wh, out);
}

// round 9
// speedup vs baseline: 2.5454x; 1.0797x over previous
#include <cuda_runtime.h>
#include <cstdint>

#define B_ 64
#define T_ 1024
#define I_ 256
#define H_ 512

typedef unsigned long long u64;

// ---------------- packed f32x2 helpers (sm_103a) ----------------
__device__ __forceinline__ u64 pack2(float lo, float hi) {
    u64 r; asm("mov.b64 %0, {%1, %2};" : "=l"(r) : "f"(lo), "f"(hi)); return r;
}
__device__ __forceinline__ u64 fma2(u64 a, u64 b, u64 c) {
    u64 d; asm("fma.rn.f32x2 %0, %1, %2, %3;" : "=l"(d) : "l"(a), "l"(b), "l"(c)); return d;
}
__device__ __forceinline__ u64 add2(u64 a, u64 b) {
    u64 d; asm("add.rn.f32x2 %0, %1, %2;" : "=l"(d) : "l"(a), "l"(b)); return d;
}
__device__ __forceinline__ float2 unpack2(u64 v) {
    float2 r; asm("mov.b64 {%0, %1}, %2;" : "=f"(r.x), "=f"(r.y) : "l"(v)); return r;
}

// ---------------- static device scratch (no dynamic allocation) ----------------
// Projections stored transposed: [t][j][b]  -> index (t*H_ + j)*B_ + b
__device__ float g_xz[(size_t)T_ * H_ * B_];
__device__ float g_xr[(size_t)T_ * H_ * B_];
__device__ float g_xh[(size_t)T_ * H_ * B_];
// Hidden state double buffer + r*h exchange buffer, layout [b][j]
__device__ float g_h[2][B_ * H_];
__device__ float g_rh[B_ * H_];
// Per-batch-group barrier state: 4 independent slots, 128B apart.
// Statically zero-initialized; count self-resets; gen is monotone (replay-safe).
struct __align__(128) BarSlot { unsigned count; unsigned gen; unsigned pad[30]; };
__device__ BarSlot g_bar[4];

// ---------------- per-batch-group barrier, scoped release/acquire ----------
// No MEMBAR.GL: ordering folded into the atomics. Standard generation barrier:
// read gen (acquire) -> release-arrive on count -> last resets count (relaxed)
// and release-publishes gen+1; others acquire-poll gen. bar.sync propagates
// thread 0's observations to the whole CTA (CTA-scope acq_rel, cumulative).
__device__ __forceinline__ void group_sync_(int bg) {
    __syncthreads();
    if (threadIdx.x == 0) {
        unsigned* cnt  = &g_bar[bg].count;
        unsigned* genp = &g_bar[bg].gen;
        unsigned g0, old, v;
        asm volatile("ld.acquire.gpu.u32 %0, [%1];" : "=r"(g0) : "l"(genp) : "memory");
        asm volatile("atom.release.gpu.add.u32 %0, [%1], %2;"
                     : "=r"(old) : "l"(cnt), "r"(1u) : "memory");
        if (old == 31u) {
            asm volatile("st.relaxed.gpu.u32 [%0], %1;" :: "l"(cnt), "r"(0u) : "memory");
            asm volatile("st.release.gpu.u32 [%0], %1;" :: "l"(genp), "r"(g0 + 1u) : "memory");
        } else {
            do {
                asm volatile("ld.acquire.gpu.u32 %0, [%1];" : "=r"(v) : "l"(genp) : "memory");
            } while (v == g0);
        }
    }
    __syncthreads();
}

// =================================================================================
// Projection GEMM:  out_g[t][n][b] = xs[b][t][:] . Wg[0:I][n] + bias_g[n]
// =================================================================================
__global__ __launch_bounds__(256) void gru_proj_kernel(
    const float* __restrict__ xs,
    const float* __restrict__ Wz, const float* __restrict__ Wr, const float* __restrict__ Wh,
    const float* __restrict__ bz, const float* __restrict__ br, const float* __restrict__ bh)
{
    __shared__ float As[8 * 132];
    __shared__ float Bs[8 * 132];

    const int g = blockIdx.z;
    const float* W    = (g == 0) ? Wz : (g == 1) ? Wr : Wh;
    const float* bias = (g == 0) ? bz : (g == 1) ? br : bh;
    float*       out  = (g == 0) ? g_xz : (g == 1) ? g_xr : g_xh;

    const int m0 = blockIdx.x * 128;
    const int n0 = blockIdx.y * 128;
    const int tid = (int)threadIdx.x;

    const int tx = tid & 15;
    const int ty = tid >> 4;

    const int arow = tid >> 1, aseg = tid & 1;
    const int brow = tid >> 5, bcol4 = (tid & 31) * 4;

    u64 acc2[8][4];
#pragma unroll
    for (int i = 0; i < 8; ++i)
#pragma unroll
        for (int j = 0; j < 4; ++j) acc2[i][j] = 0ull;

    for (int k0 = 0; k0 < I_; k0 += 8) {
        float4 av = *(const float4*)&xs[(size_t)(m0 + arow) * I_ + k0 + aseg * 4];
        float4 bv = *(const float4*)&W[(size_t)(k0 + brow) * H_ + n0 + bcol4];
        __syncthreads();
        As[(aseg * 4 + 0) * 132 + arow] = av.x;
        As[(aseg * 4 + 1) * 132 + arow] = av.y;
        As[(aseg * 4 + 2) * 132 + arow] = av.z;
        As[(aseg * 4 + 3) * 132 + arow] = av.w;
        *(float4*)&Bs[brow * 132 + bcol4] = bv;
        __syncthreads();
#pragma unroll
        for (int kk = 0; kk < 8; ++kk) {
            float a[8];
            float4 a0 = *(const float4*)&As[kk * 132 + ty * 8];
            float4 a1 = *(const float4*)&As[kk * 132 + ty * 8 + 4];
            ulonglong2 bq0 = *(const ulonglong2*)&Bs[kk * 132 + tx * 8];
            ulonglong2 bq1 = *(const ulonglong2*)&Bs[kk * 132 + tx * 8 + 4];
            a[0]=a0.x; a[1]=a0.y; a[2]=a0.z; a[3]=a0.w;
            a[4]=a1.x; a[5]=a1.y; a[6]=a1.z; a[7]=a1.w;
            u64 bp[4] = { bq0.x, bq0.y, bq1.x, bq1.y };
#pragma unroll
            for (int i = 0; i < 8; ++i) {
                u64 ap = pack2(a[i], a[i]);
#pragma unroll
                for (int j = 0; j < 4; ++j) acc2[i][j] = fma2(ap, bp[j], acc2[i][j]);
            }
        }
    }

#pragma unroll
    for (int j = 0; j < 4; ++j) {
        const int n = n0 + tx * 8 + 2 * j;
        const float bi0 = bias[n], bi1 = bias[n + 1];
#pragma unroll
        for (int i = 0; i < 8; ++i) {
            const int m = m0 + ty * 8 + i;
            const int t = m & (T_ - 1);
            const int b = m >> 10;
            float2 v = unpack2(acc2[i][j]);
            out[(size_t)(t * H_ + n) * B_ + b]     = v.x + bi0;
            out[(size_t)(t * H_ + n + 1) * B_ + b] = v.y + bi1;
        }
    }
}

// =================================================================================
// Persistent recurrence kernel: 128 CTAs (4 batch-groups x 32 col-groups), 1/SM.
// CTA (bg, cg) owns batches [bg*16, bg*16+16) and h-columns [cg*16, cg*16+16).
// =================================================================================
#define NB_CTA 16
#define NC_CTA 16
#define HS_S 520               // h_s[bl*520 + k]; scalar loads bank (8b + lane)
#define WS_S 52                // w_s[k*52 + c]; 16B aligned, quad = (13k + c/4)&7
#define SMEM_FLOATS (NB_CTA * HS_S + H_ * WS_S + 256 + 256)
#define SMEM_BYTES  (SMEM_FLOATS * 4)

__device__ __forceinline__ float sigmoidf_(float x) {
    return 1.0f / (1.0f + expf(-x));
}

// exchange-and-specialize butterfly stage on packed u64 accumulators.
#define RSTAGE64(arr, N, M, lane)                                            \
    {                                                                        \
        const bool hi_ = ((lane) & (M)) != 0;                                \
        _Pragma("unroll")                                                    \
        for (int i_ = 0; i_ < (N); ++i_) {                                   \
            u64 send_ = hi_ ? arr[i_] : arr[i_ + (N)];                       \
            u64 recv_ = __shfl_xor_sync(0xffffffffu, send_, (M));            \
            u64 keep_ = hi_ ? arr[i_ + (N)] : arr[i_];                       \
            arr[i_] = add2(keep_, recv_);                                    \
        }                                                                    \
    }

// Stage this CTA's 16-batch slice: 2048 float4, 8 per thread, LDG-batched.
__device__ __forceinline__ void stage_h_(float* h_s, const float4* __restrict__ src, int tid) {
    float4 v[8];
#pragma unroll
    for (int u = 0; u < 8; ++u)
        v[u] = __ldcg(src + tid + u * 256);
#pragma unroll
    for (int u = 0; u < 8; ++u) {
        const int i = tid + u * 256;
        const int bl = i >> 7;
        const int k4 = (i & 127) << 2;
        *(float4*)&h_s[bl * HS_S + k4] = v[u];
    }
}

__global__ __launch_bounds__(256, 1) void gru_rec_kernel(
    const float* __restrict__ Wz, const float* __restrict__ Wr, const float* __restrict__ Wh,
    float* __restrict__ out)
{
    extern __shared__ float smem[];
    float* h_s  = smem;                        // NB_CTA * 520
    float* w_s  = h_s + NB_CTA * HS_S;         // H_ * 52
    float* z_s  = w_s + H_ * WS_S;             // 16 x 16
    float* hk_s = z_s + 256;                   // 16 x 16

    const int tid  = (int)threadIdx.x;
    const int w    = tid >> 5;
    const int lane = tid & 31;
    const int bg   = (int)blockIdx.x >> 5;
    const int cg   = (int)blockIdx.x & 31;
    const int col0 = cg * NC_CTA;
    const int bc0  = bg * NB_CTA;

    const int bw = w >> 2;
    const int cw = w & 3;
    const int blbase = bw * 8;

    // ---- one-time: stage 48 weight columns (16 z | 16 r | 16 h), slots 0..47 ----
    for (int i = tid; i < H_ * 48; i += 256) {
        const int k = i / 48, c = i % 48;
        const float* W = (c < 16) ? Wz : (c < 32) ? Wr : Wh;
        w_s[k * WS_S + c] = W[(size_t)(I_ + k) * H_ + col0 + (c & 15)];
    }

    // ---- per-lane epilogue mappings ----
    // phase A: acc idx = cp*8 + b (cp = col-pair 0..3 of warp's 8 cols, b = 0..7).
    // 5-stage cascade -> lane l holds idx l: cp = l>>3, b = l&7.
    const int cpA  = lane >> 3;
    const int bA   = lane & 7;
    const int gc0  = cw * 8 + 2 * cpA;         // gate col (0-15 z, 16-31 r), even
    const int jA0  = gc0 & 15;                 // h-col local (even), pair = jA0, jA0+1
    const int blA  = blbase + bA;
    const bool isZ = cw < 2;
    const float* xpA_base = isZ ? g_xz : g_xr;
    // phase B: acc idx = cp*8 + b (cp 0..1, b 0..7); 4-stage cascade -> lane l
    // holds idx (l>>1)&15; final mask-1 add completes k-sum; parity l&1 = column.
    const int blB = blbase + ((lane >> 1) & 7);
    const int jB  = cw * 4 + 2 * ((lane >> 4) & 1) + (lane & 1);

#pragma unroll 1
    for (int t = 0; t < T_; ++t) {
        // ---- stage h slice (layout [local b][k]); t==0: h = 0 ----
        __syncthreads();   // h_s free (covers w_s staging on iter 0)
        if (t == 0) {
#pragma unroll
            for (int u = 0; u < 8; ++u) {
                const int i = tid + u * 256;
                const int bl = i >> 7, k4 = (i & 127) << 2;
                *(float4*)&h_s[bl * HS_S + k4] = make_float4(0.f, 0.f, 0.f, 0.f);
            }
        } else {
            stage_h_(h_s, (const float4*)&g_h[t & 1][(size_t)bc0 * H_], tid);
        }
        const size_t xiA = ((size_t)t * H_ + col0 + jA0) * B_ + bc0 + blA;
        float xpA0 = __ldcg(&xpA_base[xiA]);
        float xpA1 = __ldcg(&xpA_base[xiA + B_]);
        __syncthreads();

        // ---- phase A: z,r dots; warp = 4 col-pairs x 8 batches, k-split 32 ----
        u64 acc2[32];                          // idx = cp*8 + b
#pragma unroll
        for (int i = 0; i < 32; ++i) acc2[i] = 0ull;
#pragma unroll 4
        for (int it = 0; it < 16; ++it) {
            const int k = lane + (it << 5);
            ulonglong2 wq0 = *(const ulonglong2*)&w_s[k * WS_S + cw * 8];
            ulonglong2 wq1 = *(const ulonglong2*)&w_s[k * WS_S + cw * 8 + 4];
            u64 wp[4] = { wq0.x, wq0.y, wq1.x, wq1.y };
            float hv[8];
#pragma unroll
            for (int b = 0; b < 8; ++b) hv[b] = h_s[(blbase + b) * HS_S + k];
            u64 hb[8];
#pragma unroll
            for (int b = 0; b < 8; ++b) hb[b] = pack2(hv[b], hv[b]);
#pragma unroll
            for (int cp = 0; cp < 4; ++cp)
#pragma unroll
                for (int b = 0; b < 8; ++b)
                    acc2[cp * 8 + b] = fma2(wp[cp], hb[b], acc2[cp * 8 + b]);
        }
        RSTAGE64(acc2, 16, 16, lane)
        RSTAGE64(acc2,  8,  8, lane)
        RSTAGE64(acc2,  4,  4, lane)
        RSTAGE64(acc2,  2,  2, lane)
        RSTAGE64(acc2,  1,  1, lane)

        {
            float2 dot = unpack2(acc2[0]);     // cols (gc0, gc0+1), batch blA
            if (isZ) {
                z_s[blA * 16 + jA0]     = sigmoidf_(xpA0 + dot.x);
                z_s[blA * 16 + jA0 + 1] = sigmoidf_(xpA1 + dot.y);
            } else {
                const float r0 = sigmoidf_(xpA0 + dot.x);
                const float r1 = sigmoidf_(xpA1 + dot.y);
                const float h0 = h_s[blA * HS_S + col0 + jA0];
                const float h1 = h_s[blA * HS_S + col0 + jA0 + 1];
                hk_s[blA * 16 + jA0]     = h0;
                hk_s[blA * 16 + jA0 + 1] = h1;
                float2 rh2 = make_float2(r0 * h0, r1 * h1);
                __stcg((float2*)&g_rh[(size_t)(bc0 + blA) * H_ + col0 + jA0], rh2);
            }
        }
        // prefetch phase-B gate operand (independent of rh exchange)
        float xpB = __ldcg(&g_xh[((size_t)t * H_ + col0 + jB) * B_ + bc0 + blB]);
        group_sync_(bg);

        // ---- stage r*h slice ----
        stage_h_(h_s, (const float4*)&g_rh[(size_t)bc0 * H_], tid);
        __syncthreads();

        // ---- phase B: candidate dots; warp = 2 col-pairs x 8 batches ----
        u64 acc2B[16];                         // idx = cp*8 + b
#pragma unroll
        for (int i = 0; i < 16; ++i) acc2B[i] = 0ull;
#pragma unroll 4
        for (int it = 0; it < 16; ++it) {
            const int k = lane + (it << 5);
            ulonglong2 wq = *(const ulonglong2*)&w_s[k * WS_S + 32 + cw * 4];
            u64 wp[2] = { wq.x, wq.y };
            float hv[8];
#pragma unroll
            for (int b = 0; b < 8; ++b) hv[b] = h_s[(blbase + b) * HS_S + k];
            u64 hb[8];
#pragma unroll
            for (int b = 0; b < 8; ++b) hb[b] = pack2(hv[b], hv[b]);
#pragma unroll
            for (int cp = 0; cp < 2; ++cp)
#pragma unroll
                for (int b = 0; b < 8; ++b)
                    acc2B[cp * 8 + b] = fma2(wp[cp], hb[b], acc2B[cp * 8 + b]);
        }
        RSTAGE64(acc2B, 8, 16, lane)
        RSTAGE64(acc2B, 4,  8, lane)
        RSTAGE64(acc2B, 2,  4, lane)
        RSTAGE64(acc2B, 1,  2, lane)
        // final mask-1 exchange: combine complementary k-parity halves
        acc2B[0] = add2(acc2B[0], __shfl_xor_sync(0xffffffffu, acc2B[0], 1));

        {
            float2 pair = unpack2(acc2B[0]);   // cols (2cp, 2cp+1) of batch blB
            const float cand = (lane & 1) ? pair.y : pair.x;
            const float z    = z_s[blB * 16 + jB];
            const float hold = hk_s[blB * 16 + jB];
            const float ht = tanhf(xpB + cand);
            const float hn = fmaf(z, ht - hold, hold);
            const int gb = bc0 + blB;
            out[(size_t)gb * T_ * H_ + (size_t)t * H_ + col0 + jB] = hn;
            __stcg(&g_h[(t + 1) & 1][(size_t)gb * H_ + col0 + jB], hn);
            if (t == T_ - 1)
                out[(size_t)B_ * T_ * H_ + (size_t)gb * H_ + col0 + jB] = hn;
        }
        group_sync_(bg);
    }
}

// =================================================================================
extern "C" void kernel_launch(void* const* d_in, const int* in_sizes, int n_in,
                              void* d_out, int out_size) {
    const float* xs = (const float*)d_in[0];
    const float* Wz = (const float*)d_in[1];
    const float* bz = (const float*)d_in[2];
    const float* Wr = (const float*)d_in[3];
    const float* br = (const float*)d_in[4];
    const float* Wh = (const float*)d_in[5];
    const float* bh = (const float*)d_in[6];
    float* out = (float*)d_out;

    cudaFuncSetAttribute(gru_rec_kernel,
                         cudaFuncAttributeMaxDynamicSharedMemorySize, SMEM_BYTES);

    dim3 pg(T_ * B_ / 128, H_ / 128, 3);
    gru_proj_kernel<<<pg, 256>>>(xs, Wz, Wr, Wh, bz, br, bh);

    gru_rec_kernel<<<128, 256, SMEM_BYTES>>>(Wz, Wr, Wh, out);
}